// round 13
// baseline (speedup 1.0000x reference)
#include <cuda_runtime.h>
#include <cuda_fp16.h>
#include <math.h>
#include <stdint.h>

#define BB 32
#define NN 1024
#define DD 512
#define HH 8
#define HD 64
#define MR (BB * NN)
#define HBN (HH * BB)
#define SCALE 0.044194173824159216f
#define ESF (SCALE * 1.4426950408889634f)   // folded into K projection
#define LDT 72
#define TILE_B (128 * LDT * 2)      // 18432 bytes per 128-row tile
#define KV_STG (9216 + 9216 + 256)  // K tile + V tile + lrz[64] (padded)

// ---- device-global scratch -------------------------------------------------
__device__ float  g_q32[(size_t)MR * DD];
__device__ float  g_o  [(size_t)MR * DD];
__device__ float  g_x32[(size_t)MR * DD];
__device__ float  g_y32[(size_t)MR * DD];
__device__ __half g_x16 [(size_t)MR * DD];
__device__ __half g_qin16[(size_t)MR * DD];
__device__ __half g_kin16[(size_t)MR * DD];
__device__ __half g_q16[(size_t)MR * DD];
__device__ __half g_k16[(size_t)MR * DD];    // pre-scaled by ESF
__device__ __half g_v16[(size_t)MR * DD];
__device__ __half g_wt[4][DD * DD];          // W^T fp16 [n][k]
__device__ __half g_lrz[HBN * NN];           // per (hb,k): -log2(Z_k), fp16

// ---- helpers ---------------------------------------------------------------
__device__ __forceinline__ uint32_t s2u(const void* p) {
    uint32_t a;
    asm("{ .reg .u64 t; cvta.to.shared.u64 t, %1; cvt.u32.u64 %0, t; }" : "=r"(a) : "l"(p));
    return a;
}
__device__ __forceinline__ void ldsm4(uint32_t* r, uint32_t a) {
    asm volatile("ldmatrix.sync.aligned.m8n8.x4.shared.b16 {%0,%1,%2,%3}, [%4];"
        : "=r"(r[0]), "=r"(r[1]), "=r"(r[2]), "=r"(r[3]) : "r"(a));
}
__device__ __forceinline__ void ldsm4t(uint32_t* r, uint32_t a) {
    asm volatile("ldmatrix.sync.aligned.m8n8.x4.trans.shared.b16 {%0,%1,%2,%3}, [%4];"
        : "=r"(r[0]), "=r"(r[1]), "=r"(r[2]), "=r"(r[3]) : "r"(a));
}
// f32-accumulator HMMA (projections)
__device__ __forceinline__ void mma_(float* c, const uint32_t* a, uint32_t b0, uint32_t b1) {
    asm volatile("mma.sync.aligned.m16n8k16.row.col.f32.f16.f16.f32 "
        "{%0,%1,%2,%3},{%4,%5,%6,%7},{%8,%9},{%0,%1,%2,%3};"
        : "+f"(c[0]), "+f"(c[1]), "+f"(c[2]), "+f"(c[3])
        : "r"(a[0]), "r"(a[1]), "r"(a[2]), "r"(a[3]), "r"(b0), "r"(b1));
}
// f16-accumulator HMMA (attention: 2x rate, packed-half2 D)
__device__ __forceinline__ void mma_h(uint32_t* c, const uint32_t* a, uint32_t b0, uint32_t b1) {
    asm volatile("mma.sync.aligned.m16n8k16.row.col.f16.f16.f16.f16 "
        "{%0,%1},{%2,%3,%4,%5},{%6,%7},{%0,%1};"
        : "+r"(c[0]), "+r"(c[1])
        : "r"(a[0]), "r"(a[1]), "r"(a[2]), "r"(a[3]), "r"(b0), "r"(b1));
}
__device__ __forceinline__ uint32_t ex2h2(uint32_t x) {
    uint32_t r;
    asm("ex2.approx.f16x2 %0, %1;" : "=r"(r) : "r"(x));
    return r;
}
__device__ __forceinline__ uint32_t hadd2u(uint32_t a, uint32_t b) {
    __half2 r = __hadd2(*(__half2*)&a, *(__half2*)&b);
    return *(uint32_t*)&r;
}
__device__ __forceinline__ void cp16(uint32_t d, const void* s) {
    asm volatile("cp.async.cg.shared.global [%0], [%1], 16;" :: "r"(d), "l"(s) : "memory");
}
#define CPCOMMIT() asm volatile("cp.async.commit_group;" ::: "memory")
#define CPWAIT2()  asm volatile("cp.async.wait_group 2;" ::: "memory")
#define CPWAIT1()  asm volatile("cp.async.wait_group 1;" ::: "memory")
#define CPWAIT0()  asm volatile("cp.async.wait_group 0;" ::: "memory")

extern __shared__ __half dynsm[];

// ---- fused elementwise prep ------------------------------------------------
__global__ __launch_bounds__(256) void f2h(const float* __restrict__ Qin,
                                           const float* __restrict__ Kin) {
    const float* in = blockIdx.y ? Kin : Qin;
    __half* out = blockIdx.y ? g_kin16 : g_qin16;
    int i = blockIdx.x * 256 + threadIdx.x;
    float4 v = ((const float4*)in)[i];
    __half2 a = __floats2half2_rn(v.x, v.y), b = __floats2half2_rn(v.z, v.w);
    uint2 u = { *(uint32_t*)&a, *(uint32_t*)&b };
    ((uint2*)out)[i] = u;
}

__global__ __launch_bounds__(256) void wtr(const float* __restrict__ W0,
                                           const float* __restrict__ W1,
                                           const float* __restrict__ W2,
                                           const float* __restrict__ W3) {
    __shared__ float t[32][33];
    const int wz = blockIdx.z;
    const float* W = (wz == 0) ? W0 : (wz == 1) ? W1 : (wz == 2) ? W2 : W3;
    const int bx = blockIdx.x * 32, by = blockIdx.y * 32;
    const int tx = threadIdx.x & 31, ty = threadIdx.x >> 5;
    __half* Wt = g_wt[wz];
    #pragma unroll
    for (int i = 0; i < 4; i++)
        t[ty + 8 * i][tx] = W[(size_t)(bx + ty + 8 * i) * DD + by + tx];
    __syncthreads();
    #pragma unroll
    for (int i = 0; i < 4; i++)
        Wt[(size_t)(by + ty + 8 * i) * DD + bx + tx] = __float2half_rn(t[tx][ty + 8 * i]);
}

// ---- dense GEMM (triple-buffered cp.async, f32 acc) ------------------------
__global__ __launch_bounds__(256, 2)
void gemm_mma(const float* __restrict__ b0, const float* __restrict__ b1,
              const float* __restrict__ b2, int mode) {
    const int sel = mode ? 3 : blockIdx.z;
    const __half* A  = (sel == 0) ? g_qin16 : (sel == 3) ? g_x16 : g_kin16;
    const __half* Bt = g_wt[sel];
    const float* bias = (sel == 1) ? b1 : (sel == 2) ? b2 : b0;
    float*  C32 = (sel == 0) ? g_q32 : (sel == 3) ? g_y32 : nullptr;
    __half* C16 = (sel == 0) ? g_q16 : (sel == 1) ? g_k16 : (sel == 2) ? g_v16 : nullptr;
    const float cs = (sel == 1) ? ESF : 1.0f;

    const int tid = threadIdx.x, wid = tid >> 5, lane = tid & 31;
    const int wm = wid & 1, wn = wid >> 1;
    const int bm = blockIdx.y * 128, bn = blockIdx.x * 128;
    const uint32_t base = s2u(dynsm);
    const int lrA = lane & 15, lcA = (lane >> 4) * 8;
    const int lrB = (lane & 7) + ((lane >> 4) << 3), lcB = ((lane >> 3) & 1) * 8;

    auto issue = [&](int kc, int st) {
        uint32_t uA = base + st * TILE_B, uB = base + 3 * TILE_B + st * TILE_B;
        #pragma unroll
        for (int t = 0; t < 4; t++) {
            int idx = tid + t * 256, row = idx >> 3, c8 = (idx & 7) * 8;
            cp16(uA + (row * LDT + c8) * 2, &A [(size_t)(bm + row) * DD + kc * 64 + c8]);
            cp16(uB + (row * LDT + c8) * 2, &Bt[(size_t)(bn + row) * DD + kc * 64 + c8]);
        }
        CPCOMMIT();
    };

    float acc[4][4][4];
    #pragma unroll
    for (int i = 0; i < 4; i++)
        #pragma unroll
        for (int j = 0; j < 4; j++)
            #pragma unroll
            for (int k = 0; k < 4; k++) acc[i][j][k] = 0.0f;

    issue(0, 0);
    issue(1, 1);
    for (int kc = 0; kc < 8; kc++) {
        if (kc < 7) CPWAIT1(); else CPWAIT0();
        __syncthreads();
        if (kc + 2 < 8) issue(kc + 2, (kc + 2) % 3);
        const int st = kc % 3;
        const uint32_t cA = base + st * TILE_B, cB = base + 3 * TILE_B + st * TILE_B;
        #pragma unroll
        for (int kk = 0; kk < 4; kk++) {
            uint32_t af[4][4];
            #pragma unroll
            for (int mt = 0; mt < 4; mt++)
                ldsm4(af[mt], cA + ((wm * 64 + mt * 16 + lrA) * LDT + kk * 16 + lcA) * 2);
            #pragma unroll
            for (int p = 0; p < 2; p++) {
                uint32_t bf[4];
                ldsm4(bf, cB + ((wn * 32 + p * 16 + lrB) * LDT + kk * 16 + lcB) * 2);
                #pragma unroll
                for (int mt = 0; mt < 4; mt++) {
                    mma_(acc[mt][p * 2],     af[mt], bf[0], bf[1]);
                    mma_(acc[mt][p * 2 + 1], af[mt], bf[2], bf[3]);
                }
            }
        }
    }
    #pragma unroll
    for (int mt = 0; mt < 4; mt++) {
        int r0 = bm + wm * 64 + mt * 16 + (lane >> 2);
        #pragma unroll
        for (int nt = 0; nt < 4; nt++) {
            int c = bn + wn * 32 + nt * 8 + (lane & 3) * 2;
            float2 bb = *(const float2*)&bias[c];
            float d0 = acc[mt][nt][0] + bb.x, d1 = acc[mt][nt][1] + bb.y;
            float d2 = acc[mt][nt][2] + bb.x, d3 = acc[mt][nt][3] + bb.y;
            if (C32) {
                float2 o0 = {d0, d1}, o1 = {d2, d3};
                *(float2*)&C32[(size_t)r0 * DD + c] = o0;
                *(float2*)&C32[(size_t)(r0 + 8) * DD + c] = o1;
            }
            if (C16) {
                __half2 h0 = __floats2half2_rn(d0 * cs, d1 * cs);
                __half2 h1 = __floats2half2_rn(d2 * cs, d3 * cs);
                *(__half2*)&C16[(size_t)r0 * DD + c] = h0;
                *(__half2*)&C16[(size_t)(r0 + 8) * DD + c] = h1;
            }
        }
    }
}

// ---- pass 1: lrz_k = -log2( sum_q 2^(s_es) )  (f16-acc QK MMA) -------------
// dyn smem: K @0 ; Q stages @18432, 36864, 55296 (73728 B)
__global__ __launch_bounds__(256, 3)
void stats_mma() {
    const int tid = threadIdx.x, wid = tid >> 5, lane = tid & 31;
    const int hb = blockIdx.y, h = hb >> 5, b = hb & 31, kb = blockIdx.x * 128;
    const uint32_t base = s2u(dynsm);
    const uint32_t uK = base;
    const int lrA = lane & 15, lcA = (lane >> 4) * 8;
    const int lrB = (lane & 7) + ((lane >> 4) << 3), lcB = ((lane >> 3) & 1) * 8;

    auto issueQ = [&](int qc, int st) {
        uint32_t uQ = base + (1 + st) * TILE_B;
        #pragma unroll
        for (int t = 0; t < 4; t++) {
            int idx = tid + t * 256, row = idx >> 3, c8 = (idx & 7) * 8;
            cp16(uQ + (row * LDT + c8) * 2,
                 &g_q16[(size_t)(b * NN + qc * 128 + row) * DD + h * HD + c8]);
        }
        CPCOMMIT();
    };

    #pragma unroll
    for (int t = 0; t < 4; t++) {
        int idx = tid + t * 256, row = idx >> 3, c8 = (idx & 7) * 8;
        cp16(uK + (row * LDT + c8) * 2,
             &g_k16[(size_t)(b * NN + kb + row) * DD + h * HD + c8]);
    }
    CPCOMMIT();
    issueQ(0, 0);
    issueQ(1, 1);
    CPWAIT2();
    __syncthreads();
    uint32_t af[4][4];
    #pragma unroll
    for (int kk = 0; kk < 4; kk++)
        ldsm4(af[kk], uK + ((wid * 16 + lrA) * LDT + kk * 16 + lcA) * 2);

    float z0a = 0.0f, z0b = 0.0f, z1a = 0.0f, z1b = 0.0f;
    for (int qc = 0; qc < 8; qc++) {
        if (qc < 7) CPWAIT1(); else CPWAIT0();
        __syncthreads();
        if (qc + 2 < 8) issueQ(qc + 2, (qc + 2) % 3);
        const uint32_t cQ = base + (1 + qc % 3) * TILE_B;
        #pragma unroll
        for (int hlf = 0; hlf < 2; hlf++) {
            uint32_t s[8][2];
            #pragma unroll
            for (int i = 0; i < 8; i++) { s[i][0] = 0u; s[i][1] = 0u; }
            #pragma unroll
            for (int kk = 0; kk < 4; kk++) {
                #pragma unroll
                for (int p = 0; p < 4; p++) {
                    uint32_t bf[4];
                    ldsm4(bf, cQ + (((hlf * 4 + p) * 16 + lrB) * LDT + kk * 16 + lcB) * 2);
                    mma_h(s[2 * p],     af[kk], bf[0], bf[1]);
                    mma_h(s[2 * p + 1], af[kk], bf[2], bf[3]);
                }
            }
            #pragma unroll
            for (int nt = 0; nt < 8; nt += 2) {
                uint32_t e0 = ex2h2(s[nt][0]);       // k row r
                uint32_t e1 = ex2h2(s[nt + 1][0]);
                uint32_t e2 = ex2h2(s[nt][1]);       // k row r+8
                uint32_t e3 = ex2h2(s[nt + 1][1]);
                float2 f0 = __half22float2(*(__half2*)&e0);
                float2 f1 = __half22float2(*(__half2*)&e1);
                float2 f2 = __half22float2(*(__half2*)&e2);
                float2 f3 = __half22float2(*(__half2*)&e3);
                z0a += f0.x + f0.y;
                z0b += f1.x + f1.y;
                z1a += f2.x + f2.y;
                z1b += f3.x + f3.y;
            }
        }
    }
    float z0 = z0a + z0b, z1 = z1a + z1b;
    z0 += __shfl_xor_sync(0xFFFFFFFFu, z0, 1);
    z0 += __shfl_xor_sync(0xFFFFFFFFu, z0, 2);
    z1 += __shfl_xor_sync(0xFFFFFFFFu, z1, 1);
    z1 += __shfl_xor_sync(0xFFFFFFFFu, z1, 2);
    if ((lane & 3) == 0) {
        int k = kb + wid * 16 + (lane >> 2);
        g_lrz[hb * NN + k] = __float2half(-__log2f(z0));
        g_lrz[hb * NN + k + 8] = __float2half(-__log2f(z1));
    }
}

// ---- pass 2: O = qh + 2^(S_es + lrz_k) @ V  (f16-acc, ldsm.trans V) --------
// dyn smem: Q @0 ; KV stages @18432+st*KV_STG (K 9216, V 9216, lrz 128+pad)
__global__ __launch_bounds__(256, 3)
void attn_mma() {
    const int tid = threadIdx.x, wid = tid >> 5, lane = tid & 31;
    const int hb = blockIdx.y, h = hb >> 5, b = hb & 31, qb = blockIdx.x * 128;
    const uint32_t base = s2u(dynsm);
    const uint32_t uQ = base;
    const int lrA = lane & 15, lcA = (lane >> 4) * 8;
    const int lrB = (lane & 7) + ((lane >> 4) << 3), lcB = ((lane >> 3) & 1) * 8;
    const int lrV = (lane & 7) + (((lane >> 3) & 1) << 3);
    const int lcV = ((lane >> 4) & 1) * 8;

    auto issueKV = [&](int kt, int st) {
        uint32_t uK = base + TILE_B + st * KV_STG;
        uint32_t uV = uK + 9216;
        uint32_t uL = uK + 18432;
        #pragma unroll
        for (int t = 0; t < 2; t++) {
            int idx = tid + t * 256, row = idx >> 3, c8 = (idx & 7) * 8;
            cp16(uK + (row * LDT + c8) * 2,
                 &g_k16[(size_t)(b * NN + kt * 64 + row) * DD + h * HD + c8]);
            cp16(uV + (row * LDT + c8) * 2,
                 &g_v16[(size_t)(b * NN + kt * 64 + row) * DD + h * HD + c8]);
        }
        if (tid < 8)
            cp16(uL + tid * 16, &g_lrz[hb * NN + kt * 64 + tid * 8]);
        CPCOMMIT();
    };

    #pragma unroll
    for (int t = 0; t < 4; t++) {
        int idx = tid + t * 256, row = idx >> 3, c8 = (idx & 7) * 8;
        cp16(uQ + (row * LDT + c8) * 2,
             &g_q16[(size_t)(b * NN + qb + row) * DD + h * HD + c8]);
    }
    CPCOMMIT();
    issueKV(0, 0);
    issueKV(1, 1);
    CPWAIT2();
    __syncthreads();
    uint32_t af[4][4];
    #pragma unroll
    for (int kk = 0; kk < 4; kk++)
        ldsm4(af[kk], uQ + ((wid * 16 + lrA) * LDT + kk * 16 + lcA) * 2);

    uint32_t o[8][2];
    #pragma unroll
    for (int i = 0; i < 8; i++) { o[i][0] = 0u; o[i][1] = 0u; }

    for (int kt = 0; kt < 16; kt++) {
        if (kt < 15) CPWAIT1(); else CPWAIT0();
        __syncthreads();
        if (kt + 2 < 16) issueKV(kt + 2, (kt + 2) % 3);
        const int st = kt % 3;
        const uint32_t cK = base + TILE_B + st * KV_STG;
        const uint32_t cV = cK + 9216;
        const __half* sL = (const __half*)((char*)dynsm + TILE_B + st * KV_STG + 18432);

        #pragma unroll
        for (int g = 0; g < 4; g++) {
            uint32_t s0[2] = {0u, 0u}, s1[2] = {0u, 0u};
            #pragma unroll
            for (int kk = 0; kk < 4; kk++) {
                uint32_t bf[4];
                ldsm4(bf, cK + ((g * 16 + lrB) * LDT + kk * 16 + lcB) * 2);
                mma_h(s0, af[kk], bf[0], bf[1]);
                mma_h(s1, af[kk], bf[2], bf[3]);
            }
            uint32_t lo = *(const uint32_t*)&sL[g * 16 + (lane & 3) * 2];
            uint32_t hi = *(const uint32_t*)&sL[g * 16 + 8 + (lane & 3) * 2];
            uint32_t aw[4];
            aw[0] = ex2h2(hadd2u(s0[0], lo));
            aw[1] = ex2h2(hadd2u(s0[1], lo));
            aw[2] = ex2h2(hadd2u(s1[0], hi));
            aw[3] = ex2h2(hadd2u(s1[1], hi));
            #pragma unroll
            for (int p = 0; p < 4; p++) {
                uint32_t bf[4];
                ldsm4t(bf, cV + ((g * 16 + lrV) * LDT + p * 16 + lcV) * 2);
                mma_h(o[2 * p],     aw, bf[0], bf[1]);
                mma_h(o[2 * p + 1], aw, bf[2], bf[3]);
            }
        }
    }
    int q0 = b * NN + qb + wid * 16 + (lane >> 2);
    #pragma unroll
    for (int nt = 0; nt < 8; nt++) {
        int c = h * HD + nt * 8 + (lane & 3) * 2;
        float2 ov0 = __half22float2(*(__half2*)&o[nt][0]);
        float2 ov1 = __half22float2(*(__half2*)&o[nt][1]);
        float2 r0v = *(const float2*)&g_q32[(size_t)q0 * DD + c];
        float2 r1v = *(const float2*)&g_q32[(size_t)(q0 + 8) * DD + c];
        float2 o0 = {ov0.x + r0v.x, ov0.y + r0v.y};
        float2 o1 = {ov1.x + r1v.x, ov1.y + r1v.y};
        *(float2*)&g_o[(size_t)q0 * DD + c] = o0;
        *(float2*)&g_o[(size_t)(q0 + 8) * DD + c] = o1;
    }
}

// ---- LayerNorm -------------------------------------------------------------
__global__ __launch_bounds__(256)
void ln_kernel(const float* __restrict__ gamma, const float* __restrict__ beta,
               float* __restrict__ out, int mode) {
    const int row = (blockIdx.x * blockDim.x + threadIdx.x) >> 5;
    const int lane = threadIdx.x & 31;
    float4 v[4];
    if (mode == 0) {
        const float4* p = (const float4*)(g_o + (size_t)row * DD);
        #pragma unroll
        for (int i = 0; i < 4; i++) v[i] = p[lane + i * 32];
    } else {
        const float4* px = (const float4*)(g_x32 + (size_t)row * DD);
        const float4* py = (const float4*)(g_y32 + (size_t)row * DD);
        #pragma unroll
        for (int i = 0; i < 4; i++) {
            float4 a = px[lane + i * 32], bq = py[lane + i * 32];
            v[i].x = a.x + fmaxf(bq.x, 0.0f); v[i].y = a.y + fmaxf(bq.y, 0.0f);
            v[i].z = a.z + fmaxf(bq.z, 0.0f); v[i].w = a.w + fmaxf(bq.w, 0.0f);
        }
    }
    float s = 0.0f, ss = 0.0f;
    #pragma unroll
    for (int i = 0; i < 4; i++) {
        s  += v[i].x + v[i].y + v[i].z + v[i].w;
        ss += v[i].x*v[i].x + v[i].y*v[i].y + v[i].z*v[i].z + v[i].w*v[i].w;
    }
    #pragma unroll
    for (int off = 16; off > 0; off >>= 1) {
        s  += __shfl_xor_sync(0xFFFFFFFFu, s, off);
        ss += __shfl_xor_sync(0xFFFFFFFFu, ss, off);
    }
    const float mean = s * (1.0f / 512.0f);
    const float var  = ss * (1.0f / 512.0f) - mean * mean;
    const float rstd = rsqrtf(var + 1e-5f);
    #pragma unroll
    for (int i = 0; i < 4; i++) {
        int c0 = (lane + i * 32) * 4;
        float4 g4 = *(const float4*)&gamma[c0];
        float4 b4 = *(const float4*)&beta[c0];
        float4 ov;
        ov.x = (v[i].x - mean) * rstd * g4.x + b4.x;
        ov.y = (v[i].y - mean) * rstd * g4.y + b4.y;
        ov.z = (v[i].z - mean) * rstd * g4.z + b4.z;
        ov.w = (v[i].w - mean) * rstd * g4.w + b4.w;
        if (mode == 0) {
            *(float4*)(g_x32 + (size_t)row * DD + c0) = ov;
            __half2 h0 = __floats2half2_rn(ov.x, ov.y), h1 = __floats2half2_rn(ov.z, ov.w);
            uint2 u = { *(uint32_t*)&h0, *(uint32_t*)&h1 };
            *(uint2*)(g_x16 + (size_t)row * DD + c0) = u;
        } else {
            *(float4*)(out + (size_t)row * DD + c0) = ov;
        }
    }
}

// ---- launch ----------------------------------------------------------------
extern "C" void kernel_launch(void* const* d_in, const int* in_sizes, int n_in,
                              void* d_out, int out_size) {
    (void)in_sizes; (void)n_in; (void)out_size;
    const float* Q   = (const float*)d_in[0];
    const float* K   = (const float*)d_in[1];
    const float* Wq  = (const float*)d_in[2];
    const float* bq  = (const float*)d_in[3];
    const float* Wk  = (const float*)d_in[4];
    const float* bk  = (const float*)d_in[5];
    const float* Wv  = (const float*)d_in[6];
    const float* bv  = (const float*)d_in[7];
    const float* Wo  = (const float*)d_in[8];
    const float* bo  = (const float*)d_in[9];
    const float* g0  = (const float*)d_in[10];
    const float* be0 = (const float*)d_in[11];
    const float* g1  = (const float*)d_in[12];
    const float* be1 = (const float*)d_in[13];
    float* out = (float*)d_out;

    const int GEMM_SM  = 6 * TILE_B;               // 110592 B
    const int STATS_SM = 4 * TILE_B;               //  73728 B
    const int ATTN_SM  = TILE_B + 3 * KV_STG;      //  74496 B
    cudaFuncSetAttribute(gemm_mma,  cudaFuncAttributeMaxDynamicSharedMemorySize, GEMM_SM);
    cudaFuncSetAttribute(stats_mma, cudaFuncAttributeMaxDynamicSharedMemorySize, STATS_SM);
    cudaFuncSetAttribute(attn_mma,  cudaFuncAttributeMaxDynamicSharedMemorySize, ATTN_SM);

    f2h<<<dim3((MR * DD / 4) / 256, 2), 256>>>(Q, K);
    wtr<<<dim3(16, 16, 4), 256>>>(Wq, Wk, Wv, Wo);

    gemm_mma<<<dim3(4, 256, 3), 256, GEMM_SM>>>(bq, bk, bv, 0);  // QKV projections
    stats_mma<<<dim3(8, HBN), 256, STATS_SM>>>();                // g_lrz
    attn_mma<<<dim3(8, HBN), 256, ATTN_SM>>>();                  // g_o
    ln_kernel<<<MR / 8, 256>>>(g0, be0, out, 0);                 // g_x32, g_x16
    gemm_mma<<<dim3(4, 256, 1), 256, GEMM_SM>>>(bo, bo, bo, 1);  // g_y32
    ln_kernel<<<MR / 8, 256>>>(g1, be1, out, 1);                 // out
}

// round 14
// speedup vs baseline: 1.4277x; 1.4277x over previous
#include <cuda_runtime.h>
#include <cuda_fp16.h>
#include <math.h>
#include <stdint.h>

#define BB 32
#define NN 1024
#define DD 512
#define HH 8
#define HD 64
#define MR (BB * NN)
#define HBN (HH * BB)
#define SCALE 0.044194173824159216f
#define ESF (SCALE * 1.4426950408889634f)   // folded into K projection
#define LDT 72
#define TILE_B (128 * LDT * 2)      // 18432 bytes per 128-row tile
#define KV_STG (9216 + 9216 + 256)  // K tile + V tile + lrz[64]

// ---- device-global scratch -------------------------------------------------
__device__ float  g_q32[(size_t)MR * DD];
__device__ float  g_o  [(size_t)MR * DD];
__device__ float  g_x32[(size_t)MR * DD];
__device__ float  g_y32[(size_t)MR * DD];
__device__ __half g_x16 [(size_t)MR * DD];
__device__ __half g_qin16[(size_t)MR * DD];
__device__ __half g_kin16[(size_t)MR * DD];
__device__ __half g_q16[(size_t)MR * DD];
__device__ __half g_k16[(size_t)MR * DD];    // pre-scaled by ESF
__device__ __half g_v16[(size_t)MR * DD];
__device__ __half g_wt[4][DD * DD];          // W^T fp16 [n][k]
__device__ float  g_rz[HBN * NN];            // per (hb,k): -log2(Z_k)

// ---- helpers ---------------------------------------------------------------
__device__ __forceinline__ uint32_t s2u(const void* p) {
    uint32_t a;
    asm("{ .reg .u64 t; cvta.to.shared.u64 t, %1; cvt.u32.u64 %0, t; }" : "=r"(a) : "l"(p));
    return a;
}
__device__ __forceinline__ void ldsm4(uint32_t* r, uint32_t a) {
    asm volatile("ldmatrix.sync.aligned.m8n8.x4.shared.b16 {%0,%1,%2,%3}, [%4];"
        : "=r"(r[0]), "=r"(r[1]), "=r"(r[2]), "=r"(r[3]) : "r"(a));
}
__device__ __forceinline__ void ldsm4t(uint32_t* r, uint32_t a) {
    asm volatile("ldmatrix.sync.aligned.m8n8.x4.trans.shared.b16 {%0,%1,%2,%3}, [%4];"
        : "=r"(r[0]), "=r"(r[1]), "=r"(r[2]), "=r"(r[3]) : "r"(a));
}
__device__ __forceinline__ void mma_(float* c, const uint32_t* a, uint32_t b0, uint32_t b1) {
    asm volatile("mma.sync.aligned.m16n8k16.row.col.f32.f16.f16.f32 "
        "{%0,%1,%2,%3},{%4,%5,%6,%7},{%8,%9},{%0,%1,%2,%3};"
        : "+f"(c[0]), "+f"(c[1]), "+f"(c[2]), "+f"(c[3])
        : "r"(a[0]), "r"(a[1]), "r"(a[2]), "r"(a[3]), "r"(b0), "r"(b1));
}
__device__ __forceinline__ uint32_t ex2h2(uint32_t x) {
    uint32_t r;
    asm("ex2.approx.f16x2 %0, %1;" : "=r"(r) : "r"(x));
    return r;
}
__device__ __forceinline__ uint32_t packh2(float a, float b) {
    __half2 h = __floats2half2_rn(a, b);
    return *(uint32_t*)&h;
}
__device__ __forceinline__ void cp16(uint32_t d, const void* s) {
    asm volatile("cp.async.cg.shared.global [%0], [%1], 16;" :: "r"(d), "l"(s) : "memory");
}
#define CPCOMMIT() asm volatile("cp.async.commit_group;" ::: "memory")
#define CPWAIT2()  asm volatile("cp.async.wait_group 2;" ::: "memory")
#define CPWAIT1()  asm volatile("cp.async.wait_group 1;" ::: "memory")
#define CPWAIT0()  asm volatile("cp.async.wait_group 0;" ::: "memory")

extern __shared__ __half dynsm[];

// ---- fused elementwise prep ------------------------------------------------
__global__ __launch_bounds__(256) void f2h(const float* __restrict__ Qin,
                                           const float* __restrict__ Kin) {
    const float* in = blockIdx.y ? Kin : Qin;
    __half* out = blockIdx.y ? g_kin16 : g_qin16;
    int i = blockIdx.x * 256 + threadIdx.x;
    float4 v = ((const float4*)in)[i];
    __half2 a = __floats2half2_rn(v.x, v.y), b = __floats2half2_rn(v.z, v.w);
    uint2 u = { *(uint32_t*)&a, *(uint32_t*)&b };
    ((uint2*)out)[i] = u;
}

__global__ __launch_bounds__(256) void wtr(const float* __restrict__ W0,
                                           const float* __restrict__ W1,
                                           const float* __restrict__ W2,
                                           const float* __restrict__ W3) {
    __shared__ float t[32][33];
    const int wz = blockIdx.z;
    const float* W = (wz == 0) ? W0 : (wz == 1) ? W1 : (wz == 2) ? W2 : W3;
    const int bx = blockIdx.x * 32, by = blockIdx.y * 32;
    const int tx = threadIdx.x & 31, ty = threadIdx.x >> 5;
    __half* Wt = g_wt[wz];
    #pragma unroll
    for (int i = 0; i < 4; i++)
        t[ty + 8 * i][tx] = W[(size_t)(bx + ty + 8 * i) * DD + by + tx];
    __syncthreads();
    #pragma unroll
    for (int i = 0; i < 4; i++)
        Wt[(size_t)(by + ty + 8 * i) * DD + bx + tx] = __float2half_rn(t[tx][ty + 8 * i]);
}

// ---- dense GEMM (triple-buffered cp.async, 1 sync/iter) --------------------
__global__ __launch_bounds__(256, 2)
void gemm_mma(const float* __restrict__ b0, const float* __restrict__ b1,
              const float* __restrict__ b2, int mode) {
    const int sel = mode ? 3 : blockIdx.z;
    const __half* A  = (sel == 0) ? g_qin16 : (sel == 3) ? g_x16 : g_kin16;
    const __half* Bt = g_wt[sel];
    const float* bias = (sel == 1) ? b1 : (sel == 2) ? b2 : b0;
    float*  C32 = (sel == 0) ? g_q32 : (sel == 3) ? g_y32 : nullptr;
    __half* C16 = (sel == 0) ? g_q16 : (sel == 1) ? g_k16 : (sel == 2) ? g_v16 : nullptr;
    const float cs = (sel == 1) ? ESF : 1.0f;

    const int tid = threadIdx.x, wid = tid >> 5, lane = tid & 31;
    const int wm = wid & 1, wn = wid >> 1;
    const int bm = blockIdx.y * 128, bn = blockIdx.x * 128;
    const uint32_t base = s2u(dynsm);
    const int lrA = lane & 15, lcA = (lane >> 4) * 8;
    const int lrB = (lane & 7) + ((lane >> 4) << 3), lcB = ((lane >> 3) & 1) * 8;

    auto issue = [&](int kc, int st) {
        uint32_t uA = base + st * TILE_B, uB = base + 3 * TILE_B + st * TILE_B;
        #pragma unroll
        for (int t = 0; t < 4; t++) {
            int idx = tid + t * 256, row = idx >> 3, c8 = (idx & 7) * 8;
            cp16(uA + (row * LDT + c8) * 2, &A [(size_t)(bm + row) * DD + kc * 64 + c8]);
            cp16(uB + (row * LDT + c8) * 2, &Bt[(size_t)(bn + row) * DD + kc * 64 + c8]);
        }
        CPCOMMIT();
    };

    float acc[4][4][4];
    #pragma unroll
    for (int i = 0; i < 4; i++)
        #pragma unroll
        for (int j = 0; j < 4; j++)
            #pragma unroll
            for (int k = 0; k < 4; k++) acc[i][j][k] = 0.0f;

    issue(0, 0);
    issue(1, 1);
    for (int kc = 0; kc < 8; kc++) {
        if (kc < 7) CPWAIT1(); else CPWAIT0();
        __syncthreads();
        if (kc + 2 < 8) issue(kc + 2, (kc + 2) % 3);
        const int st = kc % 3;
        const uint32_t cA = base + st * TILE_B, cB = base + 3 * TILE_B + st * TILE_B;
        #pragma unroll
        for (int kk = 0; kk < 4; kk++) {
            uint32_t af[4][4];
            #pragma unroll
            for (int mt = 0; mt < 4; mt++)
                ldsm4(af[mt], cA + ((wm * 64 + mt * 16 + lrA) * LDT + kk * 16 + lcA) * 2);
            #pragma unroll
            for (int p = 0; p < 2; p++) {
                uint32_t bf[4];
                ldsm4(bf, cB + ((wn * 32 + p * 16 + lrB) * LDT + kk * 16 + lcB) * 2);
                #pragma unroll
                for (int mt = 0; mt < 4; mt++) {
                    mma_(acc[mt][p * 2],     af[mt], bf[0], bf[1]);
                    mma_(acc[mt][p * 2 + 1], af[mt], bf[2], bf[3]);
                }
            }
        }
    }
    #pragma unroll
    for (int mt = 0; mt < 4; mt++) {
        int r0 = bm + wm * 64 + mt * 16 + (lane >> 2);
        #pragma unroll
        for (int nt = 0; nt < 4; nt++) {
            int c = bn + wn * 32 + nt * 8 + (lane & 3) * 2;
            float2 bb = *(const float2*)&bias[c];
            float d0 = acc[mt][nt][0] + bb.x, d1 = acc[mt][nt][1] + bb.y;
            float d2 = acc[mt][nt][2] + bb.x, d3 = acc[mt][nt][3] + bb.y;
            if (C32) {
                float2 o0 = {d0, d1}, o1 = {d2, d3};
                *(float2*)&C32[(size_t)r0 * DD + c] = o0;
                *(float2*)&C32[(size_t)(r0 + 8) * DD + c] = o1;
            }
            if (C16) {
                __half2 h0 = __floats2half2_rn(d0 * cs, d1 * cs);
                __half2 h1 = __floats2half2_rn(d2 * cs, d3 * cs);
                *(__half2*)&C16[(size_t)r0 * DD + c] = h0;
                *(__half2*)&C16[(size_t)(r0 + 8) * DD + c] = h1;
            }
        }
    }
}

// ---- pass 1: lrz_k = -log2( sum_q 2^(s_es) ) -------------------------------
// dyn smem: K @0 ; Q stages @18432, 36864, 55296 (73728 B)
__global__ __launch_bounds__(256, 3)
void stats_mma() {
    const int tid = threadIdx.x, wid = tid >> 5, lane = tid & 31;
    const int hb = blockIdx.y, h = hb >> 5, b = hb & 31, kb = blockIdx.x * 128;
    const uint32_t base = s2u(dynsm);
    const uint32_t uK = base;
    const int lrA = lane & 15, lcA = (lane >> 4) * 8;
    const int lrB = (lane & 7) + ((lane >> 4) << 3), lcB = ((lane >> 3) & 1) * 8;

    auto issueQ = [&](int qc, int st) {
        uint32_t uQ = base + (1 + st) * TILE_B;
        #pragma unroll
        for (int t = 0; t < 4; t++) {
            int idx = tid + t * 256, row = idx >> 3, c8 = (idx & 7) * 8;
            cp16(uQ + (row * LDT + c8) * 2,
                 &g_q16[(size_t)(b * NN + qc * 128 + row) * DD + h * HD + c8]);
        }
        CPCOMMIT();
    };

    #pragma unroll
    for (int t = 0; t < 4; t++) {
        int idx = tid + t * 256, row = idx >> 3, c8 = (idx & 7) * 8;
        cp16(uK + (row * LDT + c8) * 2,
             &g_k16[(size_t)(b * NN + kb + row) * DD + h * HD + c8]);
    }
    CPCOMMIT();
    issueQ(0, 0);
    issueQ(1, 1);
    CPWAIT2();
    __syncthreads();
    uint32_t af[4][4];
    #pragma unroll
    for (int kk = 0; kk < 4; kk++)
        ldsm4(af[kk], uK + ((wid * 16 + lrA) * LDT + kk * 16 + lcA) * 2);

    float z0a = 0.0f, z0b = 0.0f, z1a = 0.0f, z1b = 0.0f;
    for (int qc = 0; qc < 8; qc++) {
        if (qc < 7) CPWAIT1(); else CPWAIT0();
        __syncthreads();
        if (qc + 2 < 8) issueQ(qc + 2, (qc + 2) % 3);
        const uint32_t cQ = base + (1 + qc % 3) * TILE_B;
        #pragma unroll
        for (int hlf = 0; hlf < 2; hlf++) {
            float s[8][4];
            #pragma unroll
            for (int i = 0; i < 8; i++)
                #pragma unroll
                for (int j = 0; j < 4; j++) s[i][j] = 0.0f;
            #pragma unroll
            for (int kk = 0; kk < 4; kk++) {
                #pragma unroll
                for (int p = 0; p < 4; p++) {
                    uint32_t bf[4];
                    ldsm4(bf, cQ + (((hlf * 4 + p) * 16 + lrB) * LDT + kk * 16 + lcB) * 2);
                    mma_(s[2 * p],     af[kk], bf[0], bf[1]);
                    mma_(s[2 * p + 1], af[kk], bf[2], bf[3]);
                }
            }
            #pragma unroll
            for (int nt = 0; nt < 8; nt += 2) {
                uint32_t e0 = ex2h2(packh2(s[nt][0],     s[nt][1]));
                uint32_t e1 = ex2h2(packh2(s[nt + 1][0], s[nt + 1][1]));
                uint32_t e2 = ex2h2(packh2(s[nt][2],     s[nt][3]));
                uint32_t e3 = ex2h2(packh2(s[nt + 1][2], s[nt + 1][3]));
                float2 f0 = __half22float2(*(__half2*)&e0);
                float2 f1 = __half22float2(*(__half2*)&e1);
                float2 f2 = __half22float2(*(__half2*)&e2);
                float2 f3 = __half22float2(*(__half2*)&e3);
                z0a += f0.x + f0.y;
                z0b += f1.x + f1.y;
                z1a += f2.x + f2.y;
                z1b += f3.x + f3.y;
            }
        }
    }
    float z0 = z0a + z0b, z1 = z1a + z1b;
    z0 += __shfl_xor_sync(0xFFFFFFFFu, z0, 1);
    z0 += __shfl_xor_sync(0xFFFFFFFFu, z0, 2);
    z1 += __shfl_xor_sync(0xFFFFFFFFu, z1, 1);
    z1 += __shfl_xor_sync(0xFFFFFFFFu, z1, 2);
    if ((lane & 3) == 0) {
        int k = kb + wid * 16 + (lane >> 2);
        g_rz[hb * NN + k] = -__log2f(z0);
        g_rz[hb * NN + k + 8] = -__log2f(z1);
    }
}

// ---- pass 2: O = qh + 2^(S_es + lrz_k) @ V (ldsm.trans, no V transpose) ----
// dyn smem: Q @0 ; KV stages @18432+st*KV_STG (K 9216, V 9216, lrz 256)
__global__ __launch_bounds__(256, 3)
void attn_mma() {
    const int tid = threadIdx.x, wid = tid >> 5, lane = tid & 31;
    const int hb = blockIdx.y, h = hb >> 5, b = hb & 31, qb = blockIdx.x * 128;
    const uint32_t base = s2u(dynsm);
    const uint32_t uQ = base;
    const int lrA = lane & 15, lcA = (lane >> 4) * 8;
    const int lrB = (lane & 7) + ((lane >> 4) << 3), lcB = ((lane >> 3) & 1) * 8;
    const int lrV = (lane & 7) + (((lane >> 3) & 1) << 3);  // k within 16
    const int lcV = ((lane >> 4) & 1) * 8;                  // d within 16

    auto issueKV = [&](int kt, int st) {
        uint32_t uK = base + TILE_B + st * KV_STG;
        uint32_t uV = uK + 9216;
        uint32_t uL = uK + 18432;
        #pragma unroll
        for (int t = 0; t < 2; t++) {
            int idx = tid + t * 256, row = idx >> 3, c8 = (idx & 7) * 8;
            cp16(uK + (row * LDT + c8) * 2,
                 &g_k16[(size_t)(b * NN + kt * 64 + row) * DD + h * HD + c8]);
            cp16(uV + (row * LDT + c8) * 2,
                 &g_v16[(size_t)(b * NN + kt * 64 + row) * DD + h * HD + c8]);
        }
        if (tid < 16)
            cp16(uL + tid * 16, &g_rz[hb * NN + kt * 64 + tid * 4]);
        CPCOMMIT();
    };

    #pragma unroll
    for (int t = 0; t < 4; t++) {
        int idx = tid + t * 256, row = idx >> 3, c8 = (idx & 7) * 8;
        cp16(uQ + (row * LDT + c8) * 2,
             &g_q16[(size_t)(b * NN + qb + row) * DD + h * HD + c8]);
    }
    CPCOMMIT();
    issueKV(0, 0);
    issueKV(1, 1);
    CPWAIT2();
    __syncthreads();
    uint32_t af[4][4];
    #pragma unroll
    for (int kk = 0; kk < 4; kk++)
        ldsm4(af[kk], uQ + ((wid * 16 + lrA) * LDT + kk * 16 + lcA) * 2);

    float o[8][4];
    #pragma unroll
    for (int i = 0; i < 8; i++)
        #pragma unroll
        for (int j = 0; j < 4; j++) o[i][j] = 0.0f;

    for (int kt = 0; kt < 16; kt++) {
        if (kt < 15) CPWAIT1(); else CPWAIT0();
        __syncthreads();
        if (kt + 2 < 16) issueKV(kt + 2, (kt + 2) % 3);
        const int st = kt % 3;
        const uint32_t cK = base + TILE_B + st * KV_STG;
        const uint32_t cV = cK + 9216;
        const float* sL = (const float*)((char*)dynsm + TILE_B + st * KV_STG + 18432);

        #pragma unroll
        for (int g = 0; g < 4; g++) {
            float s[2][4];
            #pragma unroll
            for (int j = 0; j < 4; j++) { s[0][j] = 0.0f; s[1][j] = 0.0f; }
            #pragma unroll
            for (int kk = 0; kk < 4; kk++) {
                uint32_t bf[4];
                ldsm4(bf, cK + ((g * 16 + lrB) * LDT + kk * 16 + lcB) * 2);
                mma_(s[0], af[kk], bf[0], bf[1]);
                mma_(s[1], af[kk], bf[2], bf[3]);
            }
            float2 lo = *(const float2*)&sL[g * 16 + (lane & 3) * 2];
            float2 hi = *(const float2*)&sL[g * 16 + 8 + (lane & 3) * 2];
            uint32_t aw[4];
            aw[0] = ex2h2(packh2(s[0][0] + lo.x, s[0][1] + lo.y));
            aw[1] = ex2h2(packh2(s[0][2] + lo.x, s[0][3] + lo.y));
            aw[2] = ex2h2(packh2(s[1][0] + hi.x, s[1][1] + hi.y));
            aw[3] = ex2h2(packh2(s[1][2] + hi.x, s[1][3] + hi.y));
            #pragma unroll
            for (int p = 0; p < 4; p++) {
                uint32_t bf[4];
                ldsm4t(bf, cV + ((g * 16 + lrV) * LDT + p * 16 + lcV) * 2);
                mma_(o[2 * p],     aw, bf[0], bf[1]);
                mma_(o[2 * p + 1], aw, bf[2], bf[3]);
            }
        }
    }
    int q0 = b * NN + qb + wid * 16 + (lane >> 2);
    #pragma unroll
    for (int nt = 0; nt < 8; nt++) {
        int c = h * HD + nt * 8 + (lane & 3) * 2;
        float2 r0v = *(const float2*)&g_q32[(size_t)q0 * DD + c];
        float2 r1v = *(const float2*)&g_q32[(size_t)(q0 + 8) * DD + c];
        float2 o0 = {o[nt][0] + r0v.x, o[nt][1] + r0v.y};
        float2 o1 = {o[nt][2] + r1v.x, o[nt][3] + r1v.y};
        *(float2*)&g_o[(size_t)q0 * DD + c] = o0;
        *(float2*)&g_o[(size_t)(q0 + 8) * DD + c] = o1;
    }
}

// ---- LayerNorm -------------------------------------------------------------
__global__ __launch_bounds__(256)
void ln_kernel(const float* __restrict__ gamma, const float* __restrict__ beta,
               float* __restrict__ out, int mode) {
    const int row = (blockIdx.x * blockDim.x + threadIdx.x) >> 5;
    const int lane = threadIdx.x & 31;
    float4 v[4];
    if (mode == 0) {
        const float4* p = (const float4*)(g_o + (size_t)row * DD);
        #pragma unroll
        for (int i = 0; i < 4; i++) v[i] = p[lane + i * 32];
    } else {
        const float4* px = (const float4*)(g_x32 + (size_t)row * DD);
        const float4* py = (const float4*)(g_y32 + (size_t)row * DD);
        #pragma unroll
        for (int i = 0; i < 4; i++) {
            float4 a = px[lane + i * 32], bq = py[lane + i * 32];
            v[i].x = a.x + fmaxf(bq.x, 0.0f); v[i].y = a.y + fmaxf(bq.y, 0.0f);
            v[i].z = a.z + fmaxf(bq.z, 0.0f); v[i].w = a.w + fmaxf(bq.w, 0.0f);
        }
    }
    float s = 0.0f, ss = 0.0f;
    #pragma unroll
    for (int i = 0; i < 4; i++) {
        s  += v[i].x + v[i].y + v[i].z + v[i].w;
        ss += v[i].x*v[i].x + v[i].y*v[i].y + v[i].z*v[i].z + v[i].w*v[i].w;
    }
    #pragma unroll
    for (int off = 16; off > 0; off >>= 1) {
        s  += __shfl_xor_sync(0xFFFFFFFFu, s, off);
        ss += __shfl_xor_sync(0xFFFFFFFFu, ss, off);
    }
    const float mean = s * (1.0f / 512.0f);
    const float var  = ss * (1.0f / 512.0f) - mean * mean;
    const float rstd = rsqrtf(var + 1e-5f);
    #pragma unroll
    for (int i = 0; i < 4; i++) {
        int c0 = (lane + i * 32) * 4;
        float4 g4 = *(const float4*)&gamma[c0];
        float4 b4 = *(const float4*)&beta[c0];
        float4 ov;
        ov.x = (v[i].x - mean) * rstd * g4.x + b4.x;
        ov.y = (v[i].y - mean) * rstd * g4.y + b4.y;
        ov.z = (v[i].z - mean) * rstd * g4.z + b4.z;
        ov.w = (v[i].w - mean) * rstd * g4.w + b4.w;
        if (mode == 0) {
            *(float4*)(g_x32 + (size_t)row * DD + c0) = ov;
            __half2 h0 = __floats2half2_rn(ov.x, ov.y), h1 = __floats2half2_rn(ov.z, ov.w);
            uint2 u = { *(uint32_t*)&h0, *(uint32_t*)&h1 };
            *(uint2*)(g_x16 + (size_t)row * DD + c0) = u;
        } else {
            *(float4*)(out + (size_t)row * DD + c0) = ov;
        }
    }
}

// ---- launch ----------------------------------------------------------------
extern "C" void kernel_launch(void* const* d_in, const int* in_sizes, int n_in,
                              void* d_out, int out_size) {
    (void)in_sizes; (void)n_in; (void)out_size;
    const float* Q   = (const float*)d_in[0];
    const float* K   = (const float*)d_in[1];
    const float* Wq  = (const float*)d_in[2];
    const float* bq  = (const float*)d_in[3];
    const float* Wk  = (const float*)d_in[4];
    const float* bk  = (const float*)d_in[5];
    const float* Wv  = (const float*)d_in[6];
    const float* bv  = (const float*)d_in[7];
    const float* Wo  = (const float*)d_in[8];
    const float* bo  = (const float*)d_in[9];
    const float* g0  = (const float*)d_in[10];
    const float* be0 = (const float*)d_in[11];
    const float* g1  = (const float*)d_in[12];
    const float* be1 = (const float*)d_in[13];
    float* out = (float*)d_out;

    const int GEMM_SM  = 6 * TILE_B;               // 110592 B
    const int STATS_SM = 4 * TILE_B;               //  73728 B
    const int ATTN_SM  = TILE_B + 3 * KV_STG;      //  74496 B
    cudaFuncSetAttribute(gemm_mma,  cudaFuncAttributeMaxDynamicSharedMemorySize, GEMM_SM);
    cudaFuncSetAttribute(stats_mma, cudaFuncAttributeMaxDynamicSharedMemorySize, STATS_SM);
    cudaFuncSetAttribute(attn_mma,  cudaFuncAttributeMaxDynamicSharedMemorySize, ATTN_SM);

    f2h<<<dim3((MR * DD / 4) / 256, 2), 256>>>(Q, K);
    wtr<<<dim3(16, 16, 4), 256>>>(Wq, Wk, Wv, Wo);

    gemm_mma<<<dim3(4, 256, 3), 256, GEMM_SM>>>(bq, bk, bv, 0);  // QKV projections
    stats_mma<<<dim3(8, HBN), 256, STATS_SM>>>();                // lrz
    attn_mma<<<dim3(8, HBN), 256, ATTN_SM>>>();                  // g_o
    ln_kernel<<<MR / 8, 256>>>(g0, be0, out, 0);                 // g_x32, g_x16
    gemm_mma<<<dim3(4, 256, 1), 256, GEMM_SM>>>(bo, bo, bo, 1);  // g_y32
    ln_kernel<<<MR / 8, 256>>>(g1, be1, out, 1);                 // out
}

// round 16
// speedup vs baseline: 1.4522x; 1.0172x over previous
#include <cuda_runtime.h>
#include <cuda_fp16.h>
#include <math.h>
#include <stdint.h>

#define BB 32
#define NN 1024
#define DD 512
#define HH 8
#define HD 64
#define MR (BB * NN)
#define HBN (HH * BB)
#define SCALE 0.044194173824159216f
#define ESF (SCALE * 1.4426950408889634f)   // folded into K projection
#define LDT 72
#define TILE_B (128 * LDT * 2)      // 18432 bytes per 128-row tile
#define KV_STG (9216 + 9216 + 256)  // K tile + V tile + lrz[64]

// ---- device-global scratch -------------------------------------------------
__device__ float  g_o  [(size_t)MR * DD];
__device__ float  g_x32[(size_t)MR * DD];
__device__ float  g_y32[(size_t)MR * DD];
__device__ __half g_x16 [(size_t)MR * DD];
__device__ __half g_qin16[(size_t)MR * DD];
__device__ __half g_kin16[(size_t)MR * DD];
__device__ __half g_q16[(size_t)MR * DD];
__device__ __half g_k16[(size_t)MR * DD];    // pre-scaled by ESF
__device__ __half g_v16[(size_t)MR * DD];
__device__ __half g_wt[4][DD * DD];          // W^T fp16 [n][k]
__device__ float  g_rz[HBN * NN];            // per (hb,k): -log2(Z_k)

// ---- helpers ---------------------------------------------------------------
__device__ __forceinline__ uint32_t s2u(const void* p) {
    uint32_t a;
    asm("{ .reg .u64 t; cvta.to.shared.u64 t, %1; cvt.u32.u64 %0, t; }" : "=r"(a) : "l"(p));
    return a;
}
__device__ __forceinline__ void ldsm4(uint32_t* r, uint32_t a) {
    asm volatile("ldmatrix.sync.aligned.m8n8.x4.shared.b16 {%0,%1,%2,%3}, [%4];"
        : "=r"(r[0]), "=r"(r[1]), "=r"(r[2]), "=r"(r[3]) : "r"(a));
}
__device__ __forceinline__ void ldsm4t(uint32_t* r, uint32_t a) {
    asm volatile("ldmatrix.sync.aligned.m8n8.x4.trans.shared.b16 {%0,%1,%2,%3}, [%4];"
        : "=r"(r[0]), "=r"(r[1]), "=r"(r[2]), "=r"(r[3]) : "r"(a));
}
__device__ __forceinline__ void mma_(float* c, const uint32_t* a, uint32_t b0, uint32_t b1) {
    asm volatile("mma.sync.aligned.m16n8k16.row.col.f32.f16.f16.f32 "
        "{%0,%1,%2,%3},{%4,%5,%6,%7},{%8,%9},{%0,%1,%2,%3};"
        : "+f"(c[0]), "+f"(c[1]), "+f"(c[2]), "+f"(c[3])
        : "r"(a[0]), "r"(a[1]), "r"(a[2]), "r"(a[3]), "r"(b0), "r"(b1));
}
__device__ __forceinline__ uint32_t ex2h2(uint32_t x) {
    uint32_t r;
    asm("ex2.approx.f16x2 %0, %1;" : "=r"(r) : "r"(x));
    return r;
}
__device__ __forceinline__ uint32_t packh2(float a, float b) {
    __half2 h = __floats2half2_rn(a, b);
    return *(uint32_t*)&h;
}
__device__ __forceinline__ void cp16(uint32_t d, const void* s) {
    asm volatile("cp.async.cg.shared.global [%0], [%1], 16;" :: "r"(d), "l"(s) : "memory");
}
#define CPCOMMIT() asm volatile("cp.async.commit_group;" ::: "memory")
#define CPWAIT2()  asm volatile("cp.async.wait_group 2;" ::: "memory")
#define CPWAIT1()  asm volatile("cp.async.wait_group 1;" ::: "memory")
#define CPWAIT0()  asm volatile("cp.async.wait_group 0;" ::: "memory")

extern __shared__ __half dynsm[];

// ---- fused elementwise prep ------------------------------------------------
__global__ __launch_bounds__(256) void f2h(const float* __restrict__ Qin,
                                           const float* __restrict__ Kin) {
    const float* in = blockIdx.y ? Kin : Qin;
    __half* out = blockIdx.y ? g_kin16 : g_qin16;
    int i = blockIdx.x * 256 + threadIdx.x;
    float4 v = ((const float4*)in)[i];
    __half2 a = __floats2half2_rn(v.x, v.y), b = __floats2half2_rn(v.z, v.w);
    uint2 u = { *(uint32_t*)&a, *(uint32_t*)&b };
    ((uint2*)out)[i] = u;
}

__global__ __launch_bounds__(256) void wtr(const float* __restrict__ W0,
                                           const float* __restrict__ W1,
                                           const float* __restrict__ W2,
                                           const float* __restrict__ W3) {
    __shared__ float t[32][33];
    const int wz = blockIdx.z;
    const float* W = (wz == 0) ? W0 : (wz == 1) ? W1 : (wz == 2) ? W2 : W3;
    const int bx = blockIdx.x * 32, by = blockIdx.y * 32;
    const int tx = threadIdx.x & 31, ty = threadIdx.x >> 5;
    __half* Wt = g_wt[wz];
    #pragma unroll
    for (int i = 0; i < 4; i++)
        t[ty + 8 * i][tx] = W[(size_t)(bx + ty + 8 * i) * DD + by + tx];
    __syncthreads();
    #pragma unroll
    for (int i = 0; i < 4; i++)
        Wt[(size_t)(by + ty + 8 * i) * DD + bx + tx] = __float2half_rn(t[tx][ty + 8 * i]);
}

// ---- dense GEMM (triple-buffered cp.async, 1 sync/iter) --------------------
__global__ __launch_bounds__(256, 2)
void gemm_mma(const float* __restrict__ b0, const float* __restrict__ b1,
              const float* __restrict__ b2, int mode) {
    const int sel = mode ? 3 : blockIdx.z;
    const __half* A  = (sel == 0) ? g_qin16 : (sel == 3) ? g_x16 : g_kin16;
    const __half* Bt = g_wt[sel];
    const float* bias = (sel == 1) ? b1 : (sel == 2) ? b2 : b0;
    float*  C32 = (sel == 3) ? g_y32 : nullptr;
    __half* C16 = (sel == 0) ? g_q16 : (sel == 1) ? g_k16 : (sel == 2) ? g_v16 : nullptr;
    const float cs = (sel == 1) ? ESF : 1.0f;

    const int tid = threadIdx.x, wid = tid >> 5, lane = tid & 31;
    const int wm = wid & 1, wn = wid >> 1;
    const int bm = blockIdx.y * 128, bn = blockIdx.x * 128;
    const uint32_t base = s2u(dynsm);
    const int lrA = lane & 15, lcA = (lane >> 4) * 8;
    const int lrB = (lane & 7) + ((lane >> 4) << 3), lcB = ((lane >> 3) & 1) * 8;

    auto issue = [&](int kc, int st) {
        uint32_t uA = base + st * TILE_B, uB = base + 3 * TILE_B + st * TILE_B;
        #pragma unroll
        for (int t = 0; t < 4; t++) {
            int idx = tid + t * 256, row = idx >> 3, c8 = (idx & 7) * 8;
            cp16(uA + (row * LDT + c8) * 2, &A [(size_t)(bm + row) * DD + kc * 64 + c8]);
            cp16(uB + (row * LDT + c8) * 2, &Bt[(size_t)(bn + row) * DD + kc * 64 + c8]);
        }
        CPCOMMIT();
    };

    float acc[4][4][4];
    #pragma unroll
    for (int i = 0; i < 4; i++)
        #pragma unroll
        for (int j = 0; j < 4; j++)
            #pragma unroll
            for (int k = 0; k < 4; k++) acc[i][j][k] = 0.0f;

    issue(0, 0);
    issue(1, 1);
    for (int kc = 0; kc < 8; kc++) {
        if (kc < 7) CPWAIT1(); else CPWAIT0();
        __syncthreads();
        if (kc + 2 < 8) issue(kc + 2, (kc + 2) % 3);
        const int st = kc % 3;
        const uint32_t cA = base + st * TILE_B, cB = base + 3 * TILE_B + st * TILE_B;
        #pragma unroll
        for (int kk = 0; kk < 4; kk++) {
            uint32_t af[4][4];
            #pragma unroll
            for (int mt = 0; mt < 4; mt++)
                ldsm4(af[mt], cA + ((wm * 64 + mt * 16 + lrA) * LDT + kk * 16 + lcA) * 2);
            #pragma unroll
            for (int p = 0; p < 2; p++) {
                uint32_t bf[4];
                ldsm4(bf, cB + ((wn * 32 + p * 16 + lrB) * LDT + kk * 16 + lcB) * 2);
                #pragma unroll
                for (int mt = 0; mt < 4; mt++) {
                    mma_(acc[mt][p * 2],     af[mt], bf[0], bf[1]);
                    mma_(acc[mt][p * 2 + 1], af[mt], bf[2], bf[3]);
                }
            }
        }
    }
    #pragma unroll
    for (int mt = 0; mt < 4; mt++) {
        int r0 = bm + wm * 64 + mt * 16 + (lane >> 2);
        #pragma unroll
        for (int nt = 0; nt < 4; nt++) {
            int c = bn + wn * 32 + nt * 8 + (lane & 3) * 2;
            float2 bb = *(const float2*)&bias[c];
            float d0 = acc[mt][nt][0] + bb.x, d1 = acc[mt][nt][1] + bb.y;
            float d2 = acc[mt][nt][2] + bb.x, d3 = acc[mt][nt][3] + bb.y;
            if (C32) {
                float2 o0 = {d0, d1}, o1 = {d2, d3};
                *(float2*)&C32[(size_t)r0 * DD + c] = o0;
                *(float2*)&C32[(size_t)(r0 + 8) * DD + c] = o1;
            }
            if (C16) {
                __half2 h0 = __floats2half2_rn(d0 * cs, d1 * cs);
                __half2 h1 = __floats2half2_rn(d2 * cs, d3 * cs);
                *(__half2*)&C16[(size_t)r0 * DD + c] = h0;
                *(__half2*)&C16[(size_t)(r0 + 8) * DD + c] = h1;
            }
        }
    }
}

// ---- pass 1: lrz_k = -log2( sum_q 2^(s_es) ), 4(k)x2(q) warp tiling --------
// dyn smem: K @0 ; Q stages @18432, 36864, 55296 (73728 B)
// epilogue reuses the K region (free after A-frag load) for cross-warp z
__global__ __launch_bounds__(256, 3)
void stats_mma() {
    const int tid = threadIdx.x, wid = tid >> 5, lane = tid & 31;
    const int hb = blockIdx.y, h = hb >> 5, b = hb & 31, kb = blockIdx.x * 128;
    const uint32_t base = s2u(dynsm);
    const uint32_t uK = base;
    const int wk = wid & 3, wq = wid >> 2;      // 4 k-groups x 2 q-halves
    const int lrA = lane & 15, lcA = (lane >> 4) * 8;
    const int lrB = (lane & 7) + ((lane >> 4) << 3), lcB = ((lane >> 3) & 1) * 8;

    auto issueQ = [&](int qc, int st) {
        uint32_t uQ = base + (1 + st) * TILE_B;
        #pragma unroll
        for (int t = 0; t < 4; t++) {
            int idx = tid + t * 256, row = idx >> 3, c8 = (idx & 7) * 8;
            cp16(uQ + (row * LDT + c8) * 2,
                 &g_q16[(size_t)(b * NN + qc * 128 + row) * DD + h * HD + c8]);
        }
        CPCOMMIT();
    };

    #pragma unroll
    for (int t = 0; t < 4; t++) {
        int idx = tid + t * 256, row = idx >> 3, c8 = (idx & 7) * 8;
        cp16(uK + (row * LDT + c8) * 2,
             &g_k16[(size_t)(b * NN + kb + row) * DD + h * HD + c8]);
    }
    CPCOMMIT();
    issueQ(0, 0);
    issueQ(1, 1);
    CPWAIT2();
    __syncthreads();
    uint32_t af[2][4][4];            // 2 k-tiles (32 rows) cached per warp
    #pragma unroll
    for (int mt = 0; mt < 2; mt++)
        #pragma unroll
        for (int kk = 0; kk < 4; kk++)
            ldsm4(af[mt][kk], uK + ((wk * 32 + mt * 16 + lrA) * LDT + kk * 16 + lcA) * 2);

    float z[2][2] = {{0.0f, 0.0f}, {0.0f, 0.0f}};   // [mt][rowhalf]
    for (int qc = 0; qc < 8; qc++) {
        if (qc < 7) CPWAIT1(); else CPWAIT0();
        __syncthreads();
        if (qc + 2 < 8) issueQ(qc + 2, (qc + 2) % 3);
        const uint32_t cQ = base + (1 + qc % 3) * TILE_B;
        #pragma unroll
        for (int hf = 0; hf < 2; hf++) {
            float s[2][4][4];
            #pragma unroll
            for (int i = 0; i < 2; i++)
                #pragma unroll
                for (int j = 0; j < 4; j++)
                    #pragma unroll
                    for (int k = 0; k < 4; k++) s[i][j][k] = 0.0f;
            #pragma unroll
            for (int kk = 0; kk < 4; kk++) {
                #pragma unroll
                for (int p = 0; p < 2; p++) {
                    uint32_t bf[4];
                    ldsm4(bf, cQ + ((wq * 64 + hf * 32 + p * 16 + lrB) * LDT + kk * 16 + lcB) * 2);
                    #pragma unroll
                    for (int mt = 0; mt < 2; mt++) {
                        mma_(s[mt][2 * p],     af[mt][kk], bf[0], bf[1]);
                        mma_(s[mt][2 * p + 1], af[mt][kk], bf[2], bf[3]);
                    }
                }
            }
            #pragma unroll
            for (int mt = 0; mt < 2; mt++)
                #pragma unroll
                for (int pn = 0; pn < 4; pn++) {
                    uint32_t e0 = ex2h2(packh2(s[mt][pn][0], s[mt][pn][1]));
                    uint32_t e1 = ex2h2(packh2(s[mt][pn][2], s[mt][pn][3]));
                    float2 f0 = __half22float2(*(__half2*)&e0);
                    float2 f1 = __half22float2(*(__half2*)&e1);
                    z[mt][0] += f0.x + f0.y;
                    z[mt][1] += f1.x + f1.y;
                }
        }
    }
    #pragma unroll
    for (int mt = 0; mt < 2; mt++)
        #pragma unroll
        for (int i = 0; i < 2; i++) {
            z[mt][i] += __shfl_xor_sync(0xFFFFFFFFu, z[mt][i], 1);
            z[mt][i] += __shfl_xor_sync(0xFFFFFFFFu, z[mt][i], 2);
        }
    // cross-warp combine over the 2 q-halves (reuse K region)
    float* zs = (float*)dynsm;       // 2 x 128 floats = 1 KB
    __syncthreads();
    if ((lane & 3) == 0) {
        int r = lane >> 2;           // 0..7
        zs[wq * 128 + wk * 32 + r]          = z[0][0];
        zs[wq * 128 + wk * 32 + r + 8]      = z[0][1];
        zs[wq * 128 + wk * 32 + 16 + r]     = z[1][0];
        zs[wq * 128 + wk * 32 + 16 + r + 8] = z[1][1];
    }
    __syncthreads();
    if (tid < 128) {
        float zz = zs[tid] + zs[128 + tid];
        g_rz[hb * NN + kb + tid] = -__log2f(zz);
    }
}

// ---- pass 2: O = qh + 2^(S_es + lrz_k) @ V (ldsm.trans, fp16 residual) -----
// dyn smem: Q @0 ; KV stages @18432+st*KV_STG (K 9216, V 9216, lrz 256)
__global__ __launch_bounds__(256, 3)
void attn_mma() {
    const int tid = threadIdx.x, wid = tid >> 5, lane = tid & 31;
    const int hb = blockIdx.y, h = hb >> 5, b = hb & 31, qb = blockIdx.x * 128;
    const uint32_t base = s2u(dynsm);
    const uint32_t uQ = base;
    const int lrA = lane & 15, lcA = (lane >> 4) * 8;
    const int lrB = (lane & 7) + ((lane >> 4) << 3), lcB = ((lane >> 3) & 1) * 8;
    const int lrV = (lane & 7) + (((lane >> 3) & 1) << 3);  // k within 16
    const int lcV = ((lane >> 4) & 1) * 8;                  // d within 16

    auto issueKV = [&](int kt, int st) {
        uint32_t uK = base + TILE_B + st * KV_STG;
        uint32_t uV = uK + 9216;
        uint32_t uL = uK + 18432;
        #pragma unroll
        for (int t = 0; t < 2; t++) {
            int idx = tid + t * 256, row = idx >> 3, c8 = (idx & 7) * 8;
            cp16(uK + (row * LDT + c8) * 2,
                 &g_k16[(size_t)(b * NN + kt * 64 + row) * DD + h * HD + c8]);
            cp16(uV + (row * LDT + c8) * 2,
                 &g_v16[(size_t)(b * NN + kt * 64 + row) * DD + h * HD + c8]);
        }
        if (tid < 16)
            cp16(uL + tid * 16, &g_rz[hb * NN + kt * 64 + tid * 4]);
        CPCOMMIT();
    };

    #pragma unroll
    for (int t = 0; t < 4; t++) {
        int idx = tid + t * 256, row = idx >> 3, c8 = (idx & 7) * 8;
        cp16(uQ + (row * LDT + c8) * 2,
             &g_q16[(size_t)(b * NN + qb + row) * DD + h * HD + c8]);
    }
    CPCOMMIT();
    issueKV(0, 0);
    issueKV(1, 1);
    CPWAIT2();
    __syncthreads();
    uint32_t af[4][4];
    #pragma unroll
    for (int kk = 0; kk < 4; kk++)
        ldsm4(af[kk], uQ + ((wid * 16 + lrA) * LDT + kk * 16 + lcA) * 2);

    float o[8][4];
    #pragma unroll
    for (int i = 0; i < 8; i++)
        #pragma unroll
        for (int j = 0; j < 4; j++) o[i][j] = 0.0f;

    for (int kt = 0; kt < 16; kt++) {
        if (kt < 15) CPWAIT1(); else CPWAIT0();
        __syncthreads();
        if (kt + 2 < 16) issueKV(kt + 2, (kt + 2) % 3);
        const int st = kt % 3;
        const uint32_t cK = base + TILE_B + st * KV_STG;
        const uint32_t cV = cK + 9216;
        const float* sL = (const float*)((char*)dynsm + TILE_B + st * KV_STG + 18432);

        #pragma unroll
        for (int g = 0; g < 4; g++) {
            float s[2][4];
            #pragma unroll
            for (int j = 0; j < 4; j++) { s[0][j] = 0.0f; s[1][j] = 0.0f; }
            #pragma unroll
            for (int kk = 0; kk < 4; kk++) {
                uint32_t bf[4];
                ldsm4(bf, cK + ((g * 16 + lrB) * LDT + kk * 16 + lcB) * 2);
                mma_(s[0], af[kk], bf[0], bf[1]);
                mma_(s[1], af[kk], bf[2], bf[3]);
            }
            float2 lo = *(const float2*)&sL[g * 16 + (lane & 3) * 2];
            float2 hi = *(const float2*)&sL[g * 16 + 8 + (lane & 3) * 2];
            uint32_t aw[4];
            aw[0] = ex2h2(packh2(s[0][0] + lo.x, s[0][1] + lo.y));
            aw[1] = ex2h2(packh2(s[0][2] + lo.x, s[0][3] + lo.y));
            aw[2] = ex2h2(packh2(s[1][0] + hi.x, s[1][1] + hi.y));
            aw[3] = ex2h2(packh2(s[1][2] + hi.x, s[1][3] + hi.y));
            #pragma unroll
            for (int p = 0; p < 4; p++) {
                uint32_t bf[4];
                ldsm4t(bf, cV + ((g * 16 + lrV) * LDT + p * 16 + lcV) * 2);
                mma_(o[2 * p],     aw, bf[0], bf[1]);
                mma_(o[2 * p + 1], aw, bf[2], bf[3]);
            }
        }
    }
    int q0 = b * NN + qb + wid * 16 + (lane >> 2);
    #pragma unroll
    for (int nt = 0; nt < 8; nt++) {
        int c = h * HD + nt * 8 + (lane & 3) * 2;
        __half2 q0h = *(const __half2*)&g_q16[(size_t)q0 * DD + c];
        __half2 q1h = *(const __half2*)&g_q16[(size_t)(q0 + 8) * DD + c];
        float2 r0v = __half22float2(q0h);
        float2 r1v = __half22float2(q1h);
        float2 o0 = {o[nt][0] + r0v.x, o[nt][1] + r0v.y};
        float2 o1 = {o[nt][2] + r1v.x, o[nt][3] + r1v.y};
        *(float2*)&g_o[(size_t)q0 * DD + c] = o0;
        *(float2*)&g_o[(size_t)(q0 + 8) * DD + c] = o1;
    }
}

// ---- LayerNorm -------------------------------------------------------------
__global__ __launch_bounds__(256)
void ln_kernel(const float* __restrict__ gamma, const float* __restrict__ beta,
               float* __restrict__ out, int mode) {
    const int row = (blockIdx.x * blockDim.x + threadIdx.x) >> 5;
    const int lane = threadIdx.x & 31;
    float4 v[4];
    if (mode == 0) {
        const float4* p = (const float4*)(g_o + (size_t)row * DD);
        #pragma unroll
        for (int i = 0; i < 4; i++) v[i] = p[lane + i * 32];
    } else {
        const float4* px = (const float4*)(g_x32 + (size_t)row * DD);
        const float4* py = (const float4*)(g_y32 + (size_t)row * DD);
        #pragma unroll
        for (int i = 0; i < 4; i++) {
            float4 a = px[lane + i * 32], bq = py[lane + i * 32];
            v[i].x = a.x + fmaxf(bq.x, 0.0f); v[i].y = a.y + fmaxf(bq.y, 0.0f);
            v[i].z = a.z + fmaxf(bq.z, 0.0f); v[i].w = a.w + fmaxf(bq.w, 0.0f);
        }
    }
    float s = 0.0f, ss = 0.0f;
    #pragma unroll
    for (int i = 0; i < 4; i++) {
        s  += v[i].x + v[i].y + v[i].z + v[i].w;
        ss += v[i].x*v[i].x + v[i].y*v[i].y + v[i].z*v[i].z + v[i].w*v[i].w;
    }
    #pragma unroll
    for (int off = 16; off > 0; off >>= 1) {
        s  += __shfl_xor_sync(0xFFFFFFFFu, s, off);
        ss += __shfl_xor_sync(0xFFFFFFFFu, ss, off);
    }
    const float mean = s * (1.0f / 512.0f);
    const float var  = ss * (1.0f / 512.0f) - mean * mean;
    const float rstd = rsqrtf(var + 1e-5f);
    #pragma unroll
    for (int i = 0; i < 4; i++) {
        int c0 = (lane + i * 32) * 4;
        float4 g4 = *(const float4*)&gamma[c0];
        float4 b4 = *(const float4*)&beta[c0];
        float4 ov;
        ov.x = (v[i].x - mean) * rstd * g4.x + b4.x;
        ov.y = (v[i].y - mean) * rstd * g4.y + b4.y;
        ov.z = (v[i].z - mean) * rstd * g4.z + b4.z;
        ov.w = (v[i].w - mean) * rstd * g4.w + b4.w;
        if (mode == 0) {
            *(float4*)(g_x32 + (size_t)row * DD + c0) = ov;
            __half2 h0 = __floats2half2_rn(ov.x, ov.y), h1 = __floats2half2_rn(ov.z, ov.w);
            uint2 u = { *(uint32_t*)&h0, *(uint32_t*)&h1 };
            *(uint2*)(g_x16 + (size_t)row * DD + c0) = u;
        } else {
            *(float4*)(out + (size_t)row * DD + c0) = ov;
        }
    }
}

// ---- launch ----------------------------------------------------------------
extern "C" void kernel_launch(void* const* d_in, const int* in_sizes, int n_in,
                              void* d_out, int out_size) {
    (void)in_sizes; (void)n_in; (void)out_size;
    const float* Q   = (const float*)d_in[0];
    const float* K   = (const float*)d_in[1];
    const float* Wq  = (const float*)d_in[2];
    const float* bq  = (const float*)d_in[3];
    const float* Wk  = (const float*)d_in[4];
    const float* bk  = (const float*)d_in[5];
    const float* Wv  = (const float*)d_in[6];
    const float* bv  = (const float*)d_in[7];
    const float* Wo  = (const float*)d_in[8];
    const float* bo  = (const float*)d_in[9];
    const float* g0  = (const float*)d_in[10];
    const float* be0 = (const float*)d_in[11];
    const float* g1  = (const float*)d_in[12];
    const float* be1 = (const float*)d_in[13];
    float* out = (float*)d_out;

    const int GEMM_SM  = 6 * TILE_B;               // 110592 B
    const int STATS_SM = 4 * TILE_B;               //  73728 B
    const int ATTN_SM  = TILE_B + 3 * KV_STG;      //  74496 B
    cudaFuncSetAttribute(gemm_mma,  cudaFuncAttributeMaxDynamicSharedMemorySize, GEMM_SM);
    cudaFuncSetAttribute(stats_mma, cudaFuncAttributeMaxDynamicSharedMemorySize, STATS_SM);
    cudaFuncSetAttribute(attn_mma,  cudaFuncAttributeMaxDynamicSharedMemorySize, ATTN_SM);

    f2h<<<dim3((MR * DD / 4) / 256, 2), 256>>>(Q, K);
    wtr<<<dim3(16, 16, 4), 256>>>(Wq, Wk, Wv, Wo);

    gemm_mma<<<dim3(4, 256, 3), 256, GEMM_SM>>>(bq, bk, bv, 0);  // QKV projections
    stats_mma<<<dim3(8, HBN), 256, STATS_SM>>>();                // lrz
    attn_mma<<<dim3(8, HBN), 256, ATTN_SM>>>();                  // g_o
    ln_kernel<<<MR / 8, 256>>>(g0, be0, out, 0);                 // g_x32, g_x16
    gemm_mma<<<dim3(4, 256, 1), 256, GEMM_SM>>>(bo, bo, bo, 1);  // g_y32
    ln_kernel<<<MR / 8, 256>>>(g1, be1, out, 1);                 // out
}